// round 11
// baseline (speedup 1.0000x reference)
#include <cuda_runtime.h>
#include <cuda_fp16.h>
#include <cstdint>
#include <cstddef>

#define T_ 2048
#define H_ 1024
#define F_ 512
#define E_ 32
#define K_ 4
#define NSLOT (T_*K_)
#define SLOTPAD (NSLOT+128)
#define MAXTILES 96

#define RSTRIDE 144            // bytes per smem row (64 halves + 8 pad)
#define STG_B   27648          // A 128*144 + B 64*144
#define BOFF_B  18432
#define GSMEM   (3*STG_B)      // 82944, 3-stage

// ---------------- scratch ----------------
__device__ int    g_cnt[E_];
__device__ int    g_off[E_+1];
__device__ int    g_sel[NSLOT];
__device__ float  g_wgt[NSLOT];
__device__ int    g_slotTok[SLOTPAD];
__device__ float  g_slotW[SLOTPAD];
__device__ int    g_tileE[MAXTILES];
__device__ int    g_tileM[MAXTILES];
__device__ __half g_WGh[(size_t)E_*F_*H_];
__device__ __half g_WUh[(size_t)E_*F_*H_];
__device__ __half g_WDh[(size_t)E_*H_*F_];
__device__ __half g_Xh [(size_t)T_*H_];
__device__ __half g_Hbuf16[(size_t)SLOTPAD*F_];   // gate tile, then h=relu(g)*u in place

// ---------------- helpers ----------------
__device__ __forceinline__ uint32_t smem_u32(const void* p){
    uint32_t a; asm("{ .reg .u64 t; cvta.to.shared.u64 t, %1; cvt.u32.u64 %0, t; }" : "=r"(a) : "l"(p));
    return a;
}
__device__ __forceinline__ void cpa16(uint32_t dst, const void* src){
    asm volatile("cp.async.cg.shared.global [%0], [%1], 16;" :: "r"(dst), "l"(src) : "memory");
}
#define CP_COMMIT() asm volatile("cp.async.commit_group;" ::: "memory")
#define CP_WAIT1()  asm volatile("cp.async.wait_group 1;" ::: "memory")

__device__ __forceinline__ void mma_f16(float* c, uint32_t a0,uint32_t a1,uint32_t a2,uint32_t a3,
                                        uint32_t b0,uint32_t b1){
    asm("mma.sync.aligned.m16n8k16.row.col.f32.f16.f16.f32 "
        "{%0,%1,%2,%3},{%4,%5,%6,%7},{%8,%9},{%0,%1,%2,%3};"
        : "+f"(c[0]),"+f"(c[1]),"+f"(c[2]),"+f"(c[3])
        : "r"(a0),"r"(a1),"r"(a2),"r"(a3),"r"(b0),"r"(b1));
}
__device__ __forceinline__ void ldsm4(uint32_t& r0,uint32_t& r1,uint32_t& r2,uint32_t& r3,
                                      uint32_t addr){
    asm volatile("ldmatrix.sync.aligned.m8n8.x4.shared.b16 {%0,%1,%2,%3}, [%4];"
        : "=r"(r0),"=r"(r1),"=r"(r2),"=r"(r3) : "r"(addr));
}

// ---------------- 1. fused convert(WG,WU,X) + router ------------------------
__global__ __launch_bounds__(256) void cvtrouter(const float4* __restrict__ wg,
                                                 const float4* __restrict__ wu,
                                                 const float4* __restrict__ hs,
                                                 const float* __restrict__ RI,
                                                 const float* __restrict__ WR,
                                                 float* __restrict__ logits){
    if (blockIdx.x < 128){
        int gid = blockIdx.x*256 + threadIdx.x;
        int warp = gid >> 5, lane = gid & 31;
        int t0 = warp*2;
        const float* xa = RI + (size_t)t0*H_;
        const float* xb = RI + (size_t)(t0+1)*H_;
        float4 ra[8], rb[8];
        #pragma unroll
        for (int j=0;j<8;j++){ ra[j] = *(const float4*)&xa[j*128 + lane*4];
                               rb[j] = *(const float4*)&xb[j*128 + lane*4]; }
        float l0 = 0.f, l1 = 0.f;
        for (int e=0;e<E_;e++){
            const float* w = WR + (size_t)e*H_;
            float s0=0.f, s1=0.f;
            #pragma unroll
            for (int j=0;j<8;j++){
                float4 wv = *(const float4*)&w[j*128 + lane*4];
                s0 += ra[j].x*wv.x + ra[j].y*wv.y + ra[j].z*wv.z + ra[j].w*wv.w;
                s1 += rb[j].x*wv.x + rb[j].y*wv.y + rb[j].z*wv.z + rb[j].w*wv.w;
            }
            #pragma unroll
            for (int off=16;off;off>>=1){
                s0 += __shfl_xor_sync(0xffffffffu, s0, off);
                s1 += __shfl_xor_sync(0xffffffffu, s1, off);
            }
            if (lane == e){ l0 = s0; l1 = s1; }
        }
        logits[(size_t)t0*E_ + lane]     = l0;
        logits[(size_t)(t0+1)*E_ + lane] = l1;
        #pragma unroll
        for (int tok=0; tok<2; tok++){
            int t = t0 + tok;
            float cur = (tok==0) ? l0 : l1;
            int idx = lane;
            float vsel[K_]; int isel[K_];
            #pragma unroll
            for (int k=0;k<K_;k++){
                float bv = cur; int bi = idx;
                #pragma unroll
                for (int off=16;off;off>>=1){
                    float ov = __shfl_xor_sync(0xffffffffu, bv, off);
                    int   oi = __shfl_xor_sync(0xffffffffu, bi, off);
                    if (ov > bv || (ov == bv && oi < bi)){ bv = ov; bi = oi; }
                }
                vsel[k]=bv; isel[k]=bi;
                if (idx == bi) cur = -__int_as_float(0x7f800000);
            }
            float mx = vsel[0], den = 0.f, w[K_];
            #pragma unroll
            for (int k=0;k<K_;k++){ w[k] = expf(vsel[k]-mx); den += w[k]; }
            if (lane < K_){
                g_sel[t*K_+lane] = isel[lane];
                g_wgt[t*K_+lane] = w[lane]/den;
                atomicAdd(&g_cnt[isel[lane]], 1);
            }
        }
        return;
    }
    const int NW = E_*F_*H_/8;
    const int NX = T_*H_/8;
    long c0 = ((long)(blockIdx.x-128)*256 + threadIdx.x)*4;
    if (c0 >= 2L*NW + NX) return;
    const float4* src; uint4* dst; long base;
    if      (c0 <    NW){ src=wg; dst=(uint4*)g_WGh; base=0; }
    else if (c0 < 2L*NW){ src=wu; dst=(uint4*)g_WUh; base=NW; }
    else                { src=hs; dst=(uint4*)g_Xh;  base=2L*NW; }
    long i = c0 - base;
    float4 a[8];
    #pragma unroll
    for (int j=0;j<8;j++) a[j] = src[2*i + j];
    #pragma unroll
    for (int j=0;j<4;j++){
        uint4 o;
        ((__half2*)&o)[0] = __floats2half2_rn(a[2*j].x,   a[2*j].y);
        ((__half2*)&o)[1] = __floats2half2_rn(a[2*j].z,   a[2*j].w);
        ((__half2*)&o)[2] = __floats2half2_rn(a[2*j+1].x, a[2*j+1].y);
        ((__half2*)&o)[3] = __floats2half2_rn(a[2*j+1].z, a[2*j+1].w);
        dst[i+j] = o;
    }
}

// ---------------- 2. scan + scatter + tile table (one block) ----------------
__global__ __launch_bounds__(256) void scanscatter(){
    __shared__ int soff[E_];
    __shared__ int spos[E_];
    int tid = threadIdx.x;
    if (tid < E_) spos[tid] = 0;
    if (tid == 0){
        int acc = 0;
        for (int e=0;e<E_;e++){ soff[e]=acc; g_off[e]=acc; acc += g_cnt[e]; }
        g_off[E_] = acc;
        int tt = 0;
        for (int e=0;e<E_;e++){
            int nt = (g_cnt[e]+127)>>7;
            for (int i=0;i<nt;i++){ g_tileE[tt]=e; g_tileM[tt]=i; tt++; }
        }
        for (; tt<MAXTILES; tt++) g_tileE[tt] = -1;
    }
    __syncthreads();
    for (int idx = tid; idx < NSLOT; idx += 256){
        int e = g_sel[idx];
        int slot = soff[e] + atomicAdd(&spos[e], 1);
        g_slotTok[slot] = idx >> 2;
        g_slotW[slot]   = g_wgt[idx];
    }
}

// ---------------- 3. unified GEMM: 128x64 tile, frag double-buffered --------
// MODE 0: gate  -> store fp16 to Hbuf (+WD convert piggyback on extra blocks)
// MODE 1: up    -> h = relu(gate)*up, in-place into Hbuf
// MODE 2: down  -> atomicAdd wsc * C into out
template<int KDIM, int MODE>
__global__ __launch_bounds__(256,2) void gemm16(float* __restrict__ outf,
                                                const float4* __restrict__ wdsrc){
    extern __shared__ char smem[];
    int tile = blockIdx.y;
    if (MODE==0 && tile >= MAXTILES){
        long cb = (long)(tile - MAXTILES)*8 + blockIdx.x;
        long i  = (cb*256 + threadIdx.x)*4;
        float4 a[8];
        #pragma unroll
        for (int j=0;j<8;j++) a[j] = wdsrc[2*i + j];
        uint4* dst = (uint4*)g_WDh;
        #pragma unroll
        for (int j=0;j<4;j++){
            uint4 o;
            ((__half2*)&o)[0] = __floats2half2_rn(a[2*j].x,   a[2*j].y);
            ((__half2*)&o)[1] = __floats2half2_rn(a[2*j].z,   a[2*j].w);
            ((__half2*)&o)[2] = __floats2half2_rn(a[2*j+1].x, a[2*j+1].y);
            ((__half2*)&o)[3] = __floats2half2_rn(a[2*j+1].z, a[2*j+1].w);
            dst[i+j] = o;
        }
        return;
    }
    int e = g_tileE[tile];
    if (e < 0) return;
    int n0 = blockIdx.x*64;
    int m0 = g_tileM[tile]*128;
    int base = g_off[e];
    int Me   = g_off[e+1] - base;
    int tid = threadIdx.x, lane = tid&31, wid = tid>>5;
    uint32_t sb = smem_u32(smem);

    const __half* Abase = (MODE<2) ? g_Xh : g_Hbuf16;
    const __half* Wbase = (MODE==0) ? g_WGh : (MODE==1) ? g_WUh : g_WDh;
    const int WROWS = (MODE==2) ? H_ : F_;

    const __half* srcA[4]; uint32_t dofA[4];
    #pragma unroll
    for (int i=0;i<4;i++){
        int c = tid + i*256, row = c>>3, ch = c&7;
        int arow = (MODE<2) ? g_slotTok[base + m0 + row] : (base + m0 + row);
        srcA[i] = Abase + (size_t)arow*KDIM + ch*8;
        dofA[i] = (uint32_t)row*RSTRIDE + ch*16;
    }
    const __half* srcB[2]; uint32_t dofB[2];
    #pragma unroll
    for (int i=0;i<2;i++){
        int c = tid + i*256, row = c>>3, ch = c&7;
        srcB[i] = Wbase + (size_t)e*WROWS*KDIM + (size_t)(n0+row)*KDIM + ch*8;
        dofB[i] = (uint32_t)row*RSTRIDE + ch*16;
    }

    const int NKT = KDIM/64;
    #pragma unroll
    for (int kt=0; kt<2; kt++){
        uint32_t s0 = sb + kt*STG_B;
        #pragma unroll
        for (int i=0;i<4;i++) cpa16(s0 + dofA[i], srcA[i] + kt*64);
        #pragma unroll
        for (int i=0;i<2;i++) cpa16(s0 + BOFF_B + dofB[i], srcB[i] + kt*64);
        CP_COMMIT();
    }

    int g = lane>>2, tg = lane&3;
    int wm = wid&3, wn = wid>>2;
    uint32_t aOff = (uint32_t)(wm*32 + (lane&7) + ((lane>>3)&1)*8)*RSTRIDE + ((lane>>4)&1)*16;
    uint32_t bOff = (uint32_t)(wn*32 + (lane&7) + ((lane>>4)&1)*8)*RSTRIDE + ((lane>>3)&1)*16;

    float acc[2][4][4] = {};

    for (int kt=0; kt<NKT; kt++){
        CP_WAIT1();
        __syncthreads();
        if (kt+2 < NKT){
            uint32_t s0 = sb + ((kt+2)%3)*STG_B;
            int ko = (kt+2)*64;
            #pragma unroll
            for (int i=0;i<4;i++) cpa16(s0 + dofA[i], srcA[i] + ko);
            #pragma unroll
            for (int i=0;i<2;i++) cpa16(s0 + BOFF_B + dofB[i], srcB[i] + ko);
        }
        CP_COMMIT();
        int s = kt - (kt/3)*3;
        uint32_t sA = sb + s*STG_B;
        uint32_t sB = sA + BOFF_B;
        uint32_t af[2][8], bf[2][8];
        ldsm4(af[0][0],af[0][1],af[0][2],af[0][3], sA + aOff);
        ldsm4(af[0][4],af[0][5],af[0][6],af[0][7], sA + aOff + 16*RSTRIDE);
        ldsm4(bf[0][0],bf[0][1],bf[0][2],bf[0][3], sB + bOff);
        ldsm4(bf[0][4],bf[0][5],bf[0][6],bf[0][7], sB + bOff + 16*RSTRIDE);
        #pragma unroll
        for (int ks=0; ks<4; ks++){
            int cur = ks & 1, nxt = cur ^ 1;
            if (ks < 3){
                ldsm4(af[nxt][0],af[nxt][1],af[nxt][2],af[nxt][3], sA + aOff + (ks+1)*32);
                ldsm4(af[nxt][4],af[nxt][5],af[nxt][6],af[nxt][7], sA + aOff + 16*RSTRIDE + (ks+1)*32);
                ldsm4(bf[nxt][0],bf[nxt][1],bf[nxt][2],bf[nxt][3], sB + bOff + (ks+1)*32);
                ldsm4(bf[nxt][4],bf[nxt][5],bf[nxt][6],bf[nxt][7], sB + bOff + 16*RSTRIDE + (ks+1)*32);
            }
            #pragma unroll
            for (int nf=0; nf<4; nf++){
                mma_f16(acc[0][nf], af[cur][0],af[cur][1],af[cur][2],af[cur][3],
                        bf[cur][nf*2],bf[cur][nf*2+1]);
                mma_f16(acc[1][nf], af[cur][4],af[cur][5],af[cur][6],af[cur][7],
                        bf[cur][nf*2],bf[cur][nf*2+1]);
            }
        }
    }

    #pragma unroll
    for (int mt=0; mt<2; mt++){
        #pragma unroll
        for (int half=0; half<2; half++){
            int r = wm*32 + mt*16 + half*8 + g;
            if (m0 + r < Me){
                if (MODE == 0){
                    size_t ob = (size_t)(base+m0+r)*F_ + n0;
                    #pragma unroll
                    for (int nf=0; nf<4; nf++){
                        int col = wn*32 + nf*8 + 2*tg;
                        *(__half2*)&g_Hbuf16[ob + col] =
                            __floats2half2_rn(acc[mt][nf][half*2], acc[mt][nf][half*2+1]);
                    }
                } else if (MODE == 1){
                    size_t ob = (size_t)(base+m0+r)*F_ + n0;
                    #pragma unroll
                    for (int nf=0; nf<4; nf++){
                        int col = wn*32 + nf*8 + 2*tg;
                        __half2 gv = *(__half2*)&g_Hbuf16[ob + col];
                        float g0 = fmaxf(__half2float(__low2half(gv)), 0.f);
                        float g1 = fmaxf(__half2float(__high2half(gv)), 0.f);
                        *(__half2*)&g_Hbuf16[ob + col] =
                            __floats2half2_rn(g0*acc[mt][nf][half*2], g1*acc[mt][nf][half*2+1]);
                    }
                } else {
                    float wsc = g_slotW[base+m0+r];
                    int   tok = g_slotTok[base+m0+r];
                    float* orow = outf + (size_t)tok*H_ + n0;
                    #pragma unroll
                    for (int nf=0; nf<4; nf++){
                        int col = wn*32 + nf*8 + 2*tg;
                        atomicAdd(&orow[col  ], acc[mt][nf][half*2  ]*wsc);
                        atomicAdd(&orow[col+1], acc[mt][nf][half*2+1]*wsc);
                    }
                }
            }
        }
    }
}

// ---------------- launch ----------------------------------------------------
extern "C" void kernel_launch(void* const* d_in, const int* in_sizes, int n_in,
                              void* d_out, int out_size){
    const float* RI = (const float*)d_in[0];
    const float* HS = (const float*)d_in[1];
    const float* WR = (const float*)d_in[2];
    const float* WG = (const float*)d_in[3];
    const float* WU = (const float*)d_in[4];
    const float* WD = (const float*)d_in[5];
    float* out    = (float*)d_out;
    float* logits = out + (size_t)T_*H_;

    cudaFuncSetAttribute(gemm16<1024,0>, cudaFuncAttributeMaxDynamicSharedMemorySize, GSMEM);
    cudaFuncSetAttribute(gemm16<1024,1>, cudaFuncAttributeMaxDynamicSharedMemorySize, GSMEM);
    cudaFuncSetAttribute(gemm16<512, 2>, cudaFuncAttributeMaxDynamicSharedMemorySize, GSMEM);

    void* cntp; cudaGetSymbolAddress(&cntp, g_cnt);
    cudaMemsetAsync(out, 0, (size_t)T_*H_*sizeof(float));
    cudaMemsetAsync(cntp, 0, E_*sizeof(int));

    cvtrouter     <<<128+4352, 256>>>((const float4*)WG, (const float4*)WU,
                                      (const float4*)HS, RI, WR, logits);
    scanscatter   <<<1, 256>>>();
    gemm16<1024,0><<<dim3(F_/64, MAXTILES+256), 256, GSMEM>>>(nullptr, (const float4*)WD);
    gemm16<1024,1><<<dim3(F_/64, MAXTILES),     256, GSMEM>>>(nullptr, nullptr);
    gemm16<512, 2><<<dim3(H_/64, MAXTILES),     256, GSMEM>>>(out, nullptr);
}